// round 2
// baseline (speedup 1.0000x reference)
#include <cuda_runtime.h>
#include <math.h>

#define SEQ   2048
#define LCH   16
#define CE    128
#define CH    256
#define WE    512
#define WH    1024
#define NTAG  128
#define WBLOCKS 128

// ---------------- device scratch ----------------
__device__ float g_WcatT[384 * 1024];     // char [c_Wih | c_Whh]^T : [k][gate_row]
__device__ float g_cbias[1024];           // c_bih + c_bhh
__device__ float g_wbias[4096];           // w_bih + w_bhh
__device__ float g_oWT[1024 * 128];       // out_W^T : [k][tag]
__device__ float g_last[SEQ * CH];        // last char hidden per word
__device__ float g_xw[SEQ * 768];         // concat(word_emb, last_char)
__device__ float g_prew[SEQ * 4096];      // xw @ w_Wih^T + biases
__device__ float g_hs[SEQ * WH];          // word-LSTM hidden history
__device__ unsigned int g_bar;            // grid barrier counter

__device__ __forceinline__ float sigf(float x) { return 1.0f / (1.0f + __expf(-x)); }

// ---------------- prep ----------------
__global__ void prep_kernel(const float* __restrict__ cWih, const float* __restrict__ cWhh,
                            const float* __restrict__ cbih, const float* __restrict__ cbhh,
                            const float* __restrict__ wbih, const float* __restrict__ wbhh,
                            const float* __restrict__ outW)
{
    int idx = blockIdx.x * blockDim.x + threadIdx.x;
    int stride = gridDim.x * blockDim.x;
    for (int i = idx; i < 384 * 1024; i += stride) {
        int k = i >> 10, r = i & 1023;
        g_WcatT[i] = (k < CE) ? cWih[r * CE + k] : cWhh[r * CH + (k - CE)];
    }
    for (int i = idx; i < 1024; i += stride) g_cbias[i] = cbih[i] + cbhh[i];
    for (int i = idx; i < 4096; i += stride) g_wbias[i] = wbih[i] + wbhh[i];
    for (int i = idx; i < 1024 * 128; i += stride) {
        int k = i >> 7, j = i & 127;
        g_oWT[i] = outW[j * 1024 + k];
    }
    if (idx == 0) g_bar = 0u;
}

// ---------------- char LSTM ----------------
// 128 blocks x 256 threads, 16 words per block. Thread tid = hidden unit j.
// Accumulators a[4 gates][16 words]; cell state in registers.
__global__ __launch_bounds__(256, 1) void char_kernel(const int* __restrict__ char_ids,
                                                      const int* __restrict__ char_lens,
                                                      const float* __restrict__ char_emb)
{
    __shared__ float sx[384 * 16];    // xh transposed [k][word]
    __shared__ float sh[16 * CH];     // h per word
    __shared__ int   scid[16 * LCH];
    __shared__ int   slen[16];

    const int tid = threadIdx.x;
    const int wbase = blockIdx.x * 16;

    scid[tid] = char_ids[wbase * LCH + tid];
    if (tid < 16) slen[tid] = char_lens[wbase + tid];
    for (int i = tid; i < 16 * CH; i += 256) sh[i] = 0.0f;
    __syncthreads();

    const int j = tid;                 // hidden index 0..255
    float bias[4];
#pragma unroll
    for (int g = 0; g < 4; ++g) bias[g] = g_cbias[g * CH + j];

    float cst[16];
#pragma unroll
    for (int w = 0; w < 16; ++w) cst[w] = 0.0f;

    for (int t = 0; t < LCH; ++t) {
        // build xh^T [k][w]: k<128 char-emb gather, k>=128 previous h
        const int wloc = tid & 15;
        const int cid  = scid[wloc * LCH + t];
#pragma unroll
        for (int e = 0; e < 24; ++e) {
            int idx = tid + e * 256;
            int k = idx >> 4;
            float v = (k < CE) ? char_emb[cid * CE + k]
                               : sh[wloc * CH + (k - CE)];
            sx[idx] = v;
        }
        __syncthreads();

        float a[4][16];
#pragma unroll
        for (int g = 0; g < 4; ++g)
#pragma unroll
            for (int w = 0; w < 16; ++w) a[g][w] = bias[g];

#pragma unroll 2
        for (int k = 0; k < 384; ++k) {
            float w0 = g_WcatT[k * 1024 + 0 * CH + j];
            float w1 = g_WcatT[k * 1024 + 1 * CH + j];
            float w2 = g_WcatT[k * 1024 + 2 * CH + j];
            float w3 = g_WcatT[k * 1024 + 3 * CH + j];
            const float4* bp = (const float4*)&sx[k * 16];
            float4 q0 = bp[0], q1 = bp[1], q2 = bp[2], q3 = bp[3];
            float bb[16] = {q0.x,q0.y,q0.z,q0.w, q1.x,q1.y,q1.z,q1.w,
                            q2.x,q2.y,q2.z,q2.w, q3.x,q3.y,q3.z,q3.w};
#pragma unroll
            for (int w = 0; w < 16; ++w) {
                a[0][w] = fmaf(w0, bb[w], a[0][w]);
                a[1][w] = fmaf(w1, bb[w], a[1][w]);
                a[2][w] = fmaf(w2, bb[w], a[2][w]);
                a[3][w] = fmaf(w3, bb[w], a[3][w]);
            }
        }
        __syncthreads();   // done reading sh for this step

#pragma unroll
        for (int w = 0; w < 16; ++w) {
            float ig = sigf(a[0][w]);
            float fg = sigf(a[1][w]);
            float gg = tanhf(a[2][w]);
            float og = sigf(a[3][w]);
            float c = fg * cst[w] + ig * gg;
            cst[w] = c;
            float h = og * tanhf(c);
            sh[w * CH + j] = h;
            if (t == slen[w] - 1) g_last[(wbase + w) * CH + j] = h;
        }
        __syncthreads();
    }
}

// ---------------- xw concat ----------------
__global__ void xw_kernel(const int* __restrict__ word_ids, const float* __restrict__ word_emb)
{
    int t = blockIdx.x;
    int wid = word_ids[t];
    for (int i = threadIdx.x; i < 768; i += blockDim.x)
        g_xw[t * 768 + i] = (i < WE) ? word_emb[(size_t)wid * WE + i]
                                     : g_last[t * CH + (i - WE)];
}

// ---------------- pregemm: g_prew = g_xw @ w_Wih^T + wbias ----------------
// C[2048,4096], K=768. 128x128 tiles, 8x8 microtile, 256 threads.
__global__ __launch_bounds__(256, 2) void pregemm_kernel(const float* __restrict__ B)
{
    __shared__ float As[16][128];
    __shared__ float Bs[16][128];
    const int tid = threadIdx.x;
    const int tm = tid >> 4, tn = tid & 15;
    const int M0 = blockIdx.x * 128, N0 = blockIdx.y * 128;

    float acc[8][8];
#pragma unroll
    for (int i = 0; i < 8; ++i)
#pragma unroll
        for (int jj = 0; jj < 8; ++jj) acc[i][jj] = 0.0f;

    for (int k0 = 0; k0 < 768; k0 += 16) {
#pragma unroll
        for (int p = 0; p < 2; ++p) {
            int f = tid + p * 256;
            int row = f >> 2, q = f & 3;
            float4 av = *(const float4*)&g_xw[(size_t)(M0 + row) * 768 + k0 + q * 4];
            As[q*4+0][row] = av.x; As[q*4+1][row] = av.y;
            As[q*4+2][row] = av.z; As[q*4+3][row] = av.w;
            float4 bv = *(const float4*)&B[(size_t)(N0 + row) * 768 + k0 + q * 4];
            Bs[q*4+0][row] = bv.x; Bs[q*4+1][row] = bv.y;
            Bs[q*4+2][row] = bv.z; Bs[q*4+3][row] = bv.w;
        }
        __syncthreads();
#pragma unroll
        for (int k = 0; k < 16; ++k) {
            float ar[8], br[8];
            *(float4*)&ar[0] = *(const float4*)&As[k][tm * 8];
            *(float4*)&ar[4] = *(const float4*)&As[k][tm * 8 + 4];
            *(float4*)&br[0] = *(const float4*)&Bs[k][tn * 8];
            *(float4*)&br[4] = *(const float4*)&Bs[k][tn * 8 + 4];
#pragma unroll
            for (int i = 0; i < 8; ++i)
#pragma unroll
                for (int jj = 0; jj < 8; ++jj)
                    acc[i][jj] = fmaf(ar[i], br[jj], acc[i][jj]);
        }
        __syncthreads();
    }

#pragma unroll
    for (int i = 0; i < 8; ++i) {
        int m = M0 + tm * 8 + i;
#pragma unroll
        for (int jj = 0; jj < 8; ++jj) {
            int n = N0 + tn * 8 + jj;
            g_prew[(size_t)m * 4096 + n] = acc[i][jj] + g_wbias[n];
        }
    }
}

// ---------------- word LSTM recurrence (persistent, grid barrier) ----------------
// 128 blocks x 256 threads. Warp = 1 hidden unit j; 4 gates x 8 lanes each.
// Whh register-resident: 32 float4 per thread.
__global__ __launch_bounds__(256, 1) void word_kernel(const float* __restrict__ whh)
{
    __shared__ float sh[WH];
    const int tid = threadIdx.x;
    const int warp = tid >> 5, lane = tid & 31;
    const int gt = lane >> 3, li = lane & 7;
    const int j = blockIdx.x * 8 + warp;          // hidden index
    const size_t row = (size_t)(gt * WH + j);     // gate row

    float4 wv[32];
#pragma unroll
    for (int i = 0; i < 32; ++i)
        wv[i] = *(const float4*)&whh[row * WH + li * 4 + 32 * i];

    float c = 0.0f;
    unsigned int goal = 0;

    for (int t = 0; t < SEQ; ++t) {
        // stage h_{t-1}
        float4 hv4;
        if (t == 0) hv4 = make_float4(0.f, 0.f, 0.f, 0.f);
        else        hv4 = __ldcg((const float4*)&g_hs[(size_t)(t - 1) * WH + tid * 4]);
        *(float4*)&sh[tid * 4] = hv4;
        __syncthreads();

        float acc = 0.0f;
#pragma unroll
        for (int i = 0; i < 32; ++i) {
            float4 hv = *(const float4*)&sh[li * 4 + 32 * i];
            acc = fmaf(wv[i].x, hv.x, acc);
            acc = fmaf(wv[i].y, hv.y, acc);
            acc = fmaf(wv[i].z, hv.z, acc);
            acc = fmaf(wv[i].w, hv.w, acc);
        }
        acc += __shfl_down_sync(0xffffffffu, acc, 4, 8);
        acc += __shfl_down_sync(0xffffffffu, acc, 2, 8);
        acc += __shfl_down_sync(0xffffffffu, acc, 1, 8);
        // sums live on lanes 0,8,16,24 (gates i,f,g,o)

        const float* pw = &g_prew[(size_t)t * 4096 + j];
        float iv = __shfl_sync(0xffffffffu, acc, 0)  + pw[0];
        float fv = __shfl_sync(0xffffffffu, acc, 8)  + pw[1024];
        float gv = __shfl_sync(0xffffffffu, acc, 16) + pw[2048];
        float ov = __shfl_sync(0xffffffffu, acc, 24) + pw[3072];

        float ig = sigf(iv), fg = sigf(fv), og = sigf(ov), gg = tanhf(gv);
        c = fg * c + ig * gg;                      // identical on all lanes
        float h = og * tanhf(c);
        if (lane == 0) __stcg(&g_hs[(size_t)t * WH + j], h);

        __threadfence();
        __syncthreads();
        goal += WBLOCKS;
        if (tid == 0) {
            atomicAdd(&g_bar, 1u);
            while (*(volatile unsigned int*)&g_bar < goal) { }
        }
        __syncthreads();
    }
}

// ---------------- output GEMM + log_softmax ----------------
// 256 blocks x 128 threads; 8 sentence rows per block; thread = tag.
__global__ __launch_bounds__(128, 2) void out_kernel(const float* __restrict__ out_b,
                                                     float* __restrict__ out)
{
    __shared__ float shh[8 * WH];
    __shared__ float sred[4];
    const int tid = threadIdx.x;
    const int rowbase = blockIdx.x * 8;
    const int wid = tid >> 5, lane = tid & 31;

    // load 8 rows of hidden (8192 floats) via float4
#pragma unroll
    for (int q = 0; q < 16; ++q) {
        int off = (tid + q * 128) * 4;
        *(float4*)&shh[off] = *(const float4*)&g_hs[(size_t)rowbase * WH + off];
    }
    __syncthreads();

    float acc[8];
#pragma unroll
    for (int r = 0; r < 8; ++r) acc[r] = 0.0f;

    for (int k = 0; k < WH; ++k) {
        float wv = g_oWT[k * NTAG + tid];
#pragma unroll
        for (int r = 0; r < 8; ++r)
            acc[r] = fmaf(wv, shh[r * WH + k], acc[r]);
    }

    const float b = out_b[tid];
    for (int r = 0; r < 8; ++r) {
        float v = acc[r] + b;
        // row max over 128 threads
        float m = v;
#pragma unroll
        for (int o = 16; o >= 1; o >>= 1) m = fmaxf(m, __shfl_xor_sync(0xffffffffu, m, o));
        if (lane == 0) sred[wid] = m;
        __syncthreads();
        m = fmaxf(fmaxf(sred[0], sred[1]), fmaxf(sred[2], sred[3]));
        __syncthreads();
        // row sum of exp
        float e = __expf(v - m);
        float s = e;
#pragma unroll
        for (int o = 16; o >= 1; o >>= 1) s += __shfl_xor_sync(0xffffffffu, s, o);
        if (lane == 0) sred[wid] = s;
        __syncthreads();
        s = sred[0] + sred[1] + sred[2] + sred[3];
        __syncthreads();
        out[(size_t)(rowbase + r) * NTAG + tid] = v - m - __logf(s);
    }
}

// ---------------- launch ----------------
extern "C" void kernel_launch(void* const* d_in, const int* in_sizes, int n_in,
                              void* d_out, int out_size)
{
    const int*   word_ids  = (const int*)d_in[0];
    const int*   char_ids  = (const int*)d_in[1];
    const int*   char_lens = (const int*)d_in[2];
    const float* char_emb  = (const float*)d_in[3];
    const float* word_emb  = (const float*)d_in[4];
    const float* c_Wih     = (const float*)d_in[5];
    const float* c_Whh     = (const float*)d_in[6];
    const float* c_bih     = (const float*)d_in[7];
    const float* c_bhh     = (const float*)d_in[8];
    const float* w_Wih     = (const float*)d_in[9];
    const float* w_Whh     = (const float*)d_in[10];
    const float* w_bih     = (const float*)d_in[11];
    const float* w_bhh     = (const float*)d_in[12];
    const float* out_W     = (const float*)d_in[13];
    const float* out_b     = (const float*)d_in[14];
    float* out = (float*)d_out;

    prep_kernel<<<512, 256>>>(c_Wih, c_Whh, c_bih, c_bhh, w_bih, w_bhh, out_W);
    char_kernel<<<128, 256>>>(char_ids, char_lens, char_emb);
    xw_kernel<<<SEQ, 256>>>(word_ids, word_emb);
    pregemm_kernel<<<dim3(16, 32), 256>>>(w_Wih);
    word_kernel<<<WBLOCKS, 256>>>(w_Whh);
    out_kernel<<<256, 128>>>(out_b, out);
}